// round 5
// baseline (speedup 1.0000x reference)
#include <cuda_runtime.h>
#include <cstdint>

// Problem dims
#define BB   16
#define NN_  128
#define DD   1024
#define PP   128
#define P1   129     // P+1 (bias-augmented)
#define PAD  136     // padded i/j vector length (multiple of 8, >= P1)
#define W3LD (PP*PAD)  // 17408 = inner length of W3p rows / g_A rows per x

// -------- scratch (static device globals; no runtime allocation) ----------
__device__ float g_x1p[BB*NN_*PAD];                 // (b*n, i) padded, [128]=1, [129..135]=0
__device__ float g_y1p[BB*NN_*PAD];
__device__ float g_zp [BB*NN_*PP];                  // (b*n, k)
__device__ float g_W3p[PAD*W3LD];                   // (i, k*PAD+j), zero-padded
__device__ float g_A  [BB*NN_*W3LD];                // (b, x, k*PAD+j)   ~147 MB
__device__ float g_C  [BB*NN_*PP*NN_];              // (b, x, k, y)      ~134 MB

// ---------------------------------------------------------------------------
// init: build padded W3 (k-inner relayout is identity here: W3 is (i,k,j)
// row-major already, we only pad i and j to 136)
// ---------------------------------------------------------------------------
__global__ void build_w3p_kernel(const float* __restrict__ W3)
{
    int idx = blockIdx.x * blockDim.x + threadIdx.x;
    const int total = PAD * W3LD;
    if (idx >= total) return;
    int i = idx / W3LD;
    int n = idx - i * W3LD;
    int k = n / PAD;
    int j = n - k * PAD;
    float v = 0.f;
    if (i < P1 && j < P1)
        v = W3[((size_t)i * PP + k) * P1 + j];   // W3 shape (129,128,129)
    g_W3p[idx] = v;
}

__global__ void pad_init_kernel()
{
    int r = blockIdx.x * blockDim.x + threadIdx.x;
    if (r >= BB * NN_) return;
    #pragma unroll
    for (int c = P1; c < PAD; c++) {
        g_x1p[(size_t)r * PAD + c] = 0.f;
        g_y1p[(size_t)r * PAD + c] = 0.f;
    }
    g_x1p[(size_t)r * PAD + PP] = 1.f;   // bias_x column
    g_y1p[(size_t)r * PAD + PP] = 1.f;   // bias_y column
}

// ---------------------------------------------------------------------------
// Stage 0: the three MLPs (rows=2048, cols=128, K=1024), fused via gridDim.z.
// out = leaky_relu(in @ W^T + b, 0.1). 64x64 tile, 256 thr, 4x4 microtile.
// ---------------------------------------------------------------------------
__global__ __launch_bounds__(256) void mlp_kernel(
    const float* __restrict__ x,  const float* __restrict__ xs,
    const float* __restrict__ Wx, const float* __restrict__ bx,
    const float* __restrict__ Wy, const float* __restrict__ by,
    const float* __restrict__ Wz, const float* __restrict__ bz)
{
    const float *in, *W, *bias; float* outp; int ldo;
    if (blockIdx.z == 0)      { in = xs; W = Wx; bias = bx; outp = g_x1p; ldo = PAD; }
    else if (blockIdx.z == 1) { in = xs; W = Wy; bias = by; outp = g_y1p; ldo = PAD; }
    else                      { in = x;  W = Wz; bias = bz; outp = g_zp;  ldo = PP;  }

    __shared__ __align__(16) float As[8][64];
    __shared__ __align__(16) float Bs[8][64];
    const int t  = threadIdx.x;
    const int m0 = blockIdx.x * 64, n0 = blockIdx.y * 64;
    const int tr = t >> 4, tc = t & 15;
    const int lrow = t >> 2, lk = (t & 3) * 2;

    float acc[4][4] = {};
    for (int k0 = 0; k0 < DD; k0 += 8) {
        float2 a = *reinterpret_cast<const float2*>(&in[(size_t)(m0 + lrow) * DD + k0 + lk]);
        float2 w = *reinterpret_cast<const float2*>(&W [(size_t)(n0 + lrow) * DD + k0 + lk]);
        __syncthreads();
        As[lk][lrow] = a.x; As[lk + 1][lrow] = a.y;
        Bs[lk][lrow] = w.x; Bs[lk + 1][lrow] = w.y;
        __syncthreads();
        #pragma unroll
        for (int kk = 0; kk < 8; kk++) {
            float4 av = *reinterpret_cast<float4*>(&As[kk][tr * 4]);
            float4 bv = *reinterpret_cast<float4*>(&Bs[kk][tc * 4]);
            float af[4] = {av.x, av.y, av.z, av.w};
            float bf[4] = {bv.x, bv.y, bv.z, bv.w};
            #pragma unroll
            for (int i = 0; i < 4; i++)
                #pragma unroll
                for (int j = 0; j < 4; j++)
                    acc[i][j] += af[i] * bf[j];
        }
    }
    #pragma unroll
    for (int i = 0; i < 4; i++) {
        int r = m0 + tr * 4 + i;
        #pragma unroll
        for (int j = 0; j < 4; j++) {
            int c = n0 + tc * 4 + j;
            float v = acc[i][j] + bias[c];
            v = (v > 0.f) ? v : 0.1f * v;
            outp[(size_t)r * ldo + c] = v;
        }
    }
}

// ---------------------------------------------------------------------------
// Stage 1: A_b = x1p_b (128 x 136) @ W3p (136 x 17408).   NN GEMM.
// One block per (128-col tile, b). 128x128 tile, 256 thr, 8x8 microtile.
// ---------------------------------------------------------------------------
__global__ __launch_bounds__(256, 2) void s1_kernel()
{
    const int b  = blockIdx.y;
    const int n0 = blockIdx.x * 128;
    const float* __restrict__ Ab = g_x1p + (size_t)b * NN_ * PAD;

    __shared__ __align__(16) float As[8][128];
    __shared__ __align__(16) float Bs[8][128];
    const int t = threadIdx.x;
    const int tr = t >> 4, tc = t & 15;
    const int arow = t >> 1, ak = (t & 1) * 4;       // K-contig operand -> transpose on store
    const int bkk  = t >> 5, bc = (t & 31) * 4;      // N-contig operand -> direct vector store

    float acc[8][8] = {};
    for (int k0 = 0; k0 < PAD; k0 += 8) {
        float4 av = *reinterpret_cast<const float4*>(&Ab[(size_t)arow * PAD + k0 + ak]);
        float4 bv = *reinterpret_cast<const float4*>(&g_W3p[(size_t)(k0 + bkk) * W3LD + n0 + bc]);
        __syncthreads();
        As[ak + 0][arow] = av.x; As[ak + 1][arow] = av.y;
        As[ak + 2][arow] = av.z; As[ak + 3][arow] = av.w;
        *reinterpret_cast<float4*>(&Bs[bkk][bc]) = bv;
        __syncthreads();
        #pragma unroll
        for (int kk = 0; kk < 8; kk++) {
            float4 a0 = *reinterpret_cast<float4*>(&As[kk][tr * 8]);
            float4 a1 = *reinterpret_cast<float4*>(&As[kk][tr * 8 + 4]);
            float4 b0 = *reinterpret_cast<float4*>(&Bs[kk][tc * 8]);
            float4 b1 = *reinterpret_cast<float4*>(&Bs[kk][tc * 8 + 4]);
            float af[8] = {a0.x, a0.y, a0.z, a0.w, a1.x, a1.y, a1.z, a1.w};
            float bf[8] = {b0.x, b0.y, b0.z, b0.w, b1.x, b1.y, b1.z, b1.w};
            #pragma unroll
            for (int i = 0; i < 8; i++)
                #pragma unroll
                for (int j = 0; j < 8; j++)
                    acc[i][j] += af[i] * bf[j];
        }
    }
    float* __restrict__ Ob = g_A + (size_t)b * NN_ * W3LD;
    #pragma unroll
    for (int i = 0; i < 8; i++) {
        int r = tr * 8 + i;
        float4 v0 = {acc[i][0], acc[i][1], acc[i][2], acc[i][3]};
        float4 v1 = {acc[i][4], acc[i][5], acc[i][6], acc[i][7]};
        float* p = &Ob[(size_t)r * W3LD + n0 + tc * 8];
        *reinterpret_cast<float4*>(p)     = v0;
        *reinterpret_cast<float4*>(p + 4) = v1;
    }
}

// ---------------------------------------------------------------------------
// Stage 2: C[b, (x,k), y] = A[b, (x,k), j] . y1p[b, y, j].  NT GEMM, K=136.
// Rows r=(x*128+k) of g_A (ld=PAD since 128*PAD=W3LD). 128x128 tile.
// ---------------------------------------------------------------------------
__global__ __launch_bounds__(256, 2) void s2_kernel()
{
    const int b  = blockIdx.y;
    const int r0 = blockIdx.x * 128;
    const float* __restrict__ Ab = g_A   + (size_t)b * NN_ * W3LD;
    const float* __restrict__ Yb = g_y1p + (size_t)b * NN_ * PAD;

    __shared__ __align__(16) float As[8][128];
    __shared__ __align__(16) float Bs[8][128];
    const int t = threadIdx.x;
    const int tr = t >> 4, tc = t & 15;
    const int lrow = t >> 1, lk = (t & 1) * 4;

    float acc[8][8] = {};
    for (int k0 = 0; k0 < PAD; k0 += 8) {
        float4 av = *reinterpret_cast<const float4*>(&Ab[(size_t)(r0 + lrow) * PAD + k0 + lk]);
        float4 yv = *reinterpret_cast<const float4*>(&Yb[(size_t)lrow * PAD + k0 + lk]);
        __syncthreads();
        As[lk + 0][lrow] = av.x; As[lk + 1][lrow] = av.y;
        As[lk + 2][lrow] = av.z; As[lk + 3][lrow] = av.w;
        Bs[lk + 0][lrow] = yv.x; Bs[lk + 1][lrow] = yv.y;
        Bs[lk + 2][lrow] = yv.z; Bs[lk + 3][lrow] = yv.w;
        __syncthreads();
        #pragma unroll
        for (int kk = 0; kk < 8; kk++) {
            float4 a0 = *reinterpret_cast<float4*>(&As[kk][tr * 8]);
            float4 a1 = *reinterpret_cast<float4*>(&As[kk][tr * 8 + 4]);
            float4 b0 = *reinterpret_cast<float4*>(&Bs[kk][tc * 8]);
            float4 b1 = *reinterpret_cast<float4*>(&Bs[kk][tc * 8 + 4]);
            float af[8] = {a0.x, a0.y, a0.z, a0.w, a1.x, a1.y, a1.z, a1.w};
            float bf[8] = {b0.x, b0.y, b0.z, b0.w, b1.x, b1.y, b1.z, b1.w};
            #pragma unroll
            for (int i = 0; i < 8; i++)
                #pragma unroll
                for (int j = 0; j < 8; j++)
                    acc[i][j] += af[i] * bf[j];
        }
    }
    float* __restrict__ Ob = g_C + ((size_t)b * NN_ * PP + r0) * NN_;
    #pragma unroll
    for (int i = 0; i < 8; i++) {
        int r = tr * 8 + i;
        float4 v0 = {acc[i][0], acc[i][1], acc[i][2], acc[i][3]};
        float4 v1 = {acc[i][4], acc[i][5], acc[i][6], acc[i][7]};
        float* p = &Ob[(size_t)r * NN_ + tc * 8];
        *reinterpret_cast<float4*>(p)     = v0;
        *reinterpret_cast<float4*>(p + 4) = v1;
    }
}

// ---------------------------------------------------------------------------
// Stage 3: out[b,x,y,z] = sum_k C[b,x,k,y] * zp[b,z,k].  One block per (b,x).
// C tile rows are k (y contiguous -> direct load); zp is K-contig -> transpose.
// Output tile (y,z) is fully contiguous -> coalesced float4 stores, no extra
// transpose pass needed.
// ---------------------------------------------------------------------------
__global__ __launch_bounds__(256, 2) void s3_kernel(float* __restrict__ out)
{
    const int b  = blockIdx.y;
    const int xx = blockIdx.x;
    const float* __restrict__ Cm = g_C  + ((size_t)b * NN_ + xx) * (PP * NN_); // [k*128 + y]
    const float* __restrict__ Zb = g_zp + (size_t)b * NN_ * PP;                // [z*128 + k]

    __shared__ __align__(16) float Cs[8][128];
    __shared__ __align__(16) float Zs[8][128];
    const int t = threadIdx.x;
    const int tr = t >> 4, tc = t & 15;
    const int ckk  = t >> 5, cy = (t & 31) * 4;
    const int zrow = t >> 1, zk = (t & 1) * 4;

    float acc[8][8] = {};
    for (int k0 = 0; k0 < PP; k0 += 8) {
        float4 cv = *reinterpret_cast<const float4*>(&Cm[(size_t)(k0 + ckk) * NN_ + cy]);
        float4 zv = *reinterpret_cast<const float4*>(&Zb[(size_t)zrow * PP + k0 + zk]);
        __syncthreads();
        *reinterpret_cast<float4*>(&Cs[ckk][cy]) = cv;
        Zs[zk + 0][zrow] = zv.x; Zs[zk + 1][zrow] = zv.y;
        Zs[zk + 2][zrow] = zv.z; Zs[zk + 3][zrow] = zv.w;
        __syncthreads();
        #pragma unroll
        for (int kk = 0; kk < 8; kk++) {
            float4 a0 = *reinterpret_cast<float4*>(&Cs[kk][tr * 8]);      // y fragment
            float4 a1 = *reinterpret_cast<float4*>(&Cs[kk][tr * 8 + 4]);
            float4 b0 = *reinterpret_cast<float4*>(&Zs[kk][tc * 8]);      // z fragment
            float4 b1 = *reinterpret_cast<float4*>(&Zs[kk][tc * 8 + 4]);
            float af[8] = {a0.x, a0.y, a0.z, a0.w, a1.x, a1.y, a1.z, a1.w};
            float bf[8] = {b0.x, b0.y, b0.z, b0.w, b1.x, b1.y, b1.z, b1.w};
            #pragma unroll
            for (int i = 0; i < 8; i++)
                #pragma unroll
                for (int j = 0; j < 8; j++)
                    acc[i][j] += af[i] * bf[j];
        }
    }
    float* __restrict__ Ob = out + ((size_t)b * NN_ + xx) * (NN_ * PP);
    #pragma unroll
    for (int i = 0; i < 8; i++) {
        int y = tr * 8 + i;
        float4 v0 = {acc[i][0], acc[i][1], acc[i][2], acc[i][3]};
        float4 v1 = {acc[i][4], acc[i][5], acc[i][6], acc[i][7]};
        float* p = &Ob[(size_t)y * PP + tc * 8];
        *reinterpret_cast<float4*>(p)     = v0;
        *reinterpret_cast<float4*>(p + 4) = v1;
    }
}

// ---------------------------------------------------------------------------
extern "C" void kernel_launch(void* const* d_in, const int* in_sizes, int n_in,
                              void* d_out, int out_size)
{
    const float* x  = (const float*)d_in[0];
    const float* xs = (const float*)d_in[1];
    const float* Wx = (const float*)d_in[2];
    const float* bx = (const float*)d_in[3];
    const float* Wy = (const float*)d_in[4];
    const float* by = (const float*)d_in[5];
    const float* Wz = (const float*)d_in[6];
    const float* bz = (const float*)d_in[7];
    const float* W3 = (const float*)d_in[8];
    float* out = (float*)d_out;

    const int w3p_total = PAD * W3LD;
    build_w3p_kernel<<<(w3p_total + 255) / 256, 256>>>(W3);
    pad_init_kernel<<<(BB * NN_ + 255) / 256, 256>>>();
    mlp_kernel<<<dim3(BB * NN_ / 64, PP / 64, 3), 256>>>(x, xs, Wx, bx, Wy, by, Wz, bz);
    s1_kernel<<<dim3(W3LD / 128, BB), 256>>>();
    s2_kernel<<<dim3(NN_ * PP / 128, BB), 256>>>();
    s3_kernel<<<dim3(NN_, BB), 256>>>(out);
}

// round 6
// speedup vs baseline: 1.0050x; 1.0050x over previous
#include <cuda_runtime.h>
#include <cstdint>

// Problem dims
#define BB   16
#define NN_  128
#define DD   1024
#define PP   128
#define P1   129     // P+1 (bias-augmented)
#define PAD  136     // padded i/j vector length (multiple of 8, >= P1)
#define W3LD (PP*PAD)  // 17408 = inner length of W3p rows / g_A rows per x

// -------- scratch (static device globals; no runtime allocation) ----------
__device__ float g_x1p[BB*NN_*PAD];                 // (b*n, i) padded, [128]=1, [129..135]=0
__device__ float g_y1p[BB*NN_*PAD];
__device__ float g_zp [BB*NN_*PP];                  // (b*n, k)
__device__ float g_W3p[PAD*W3LD];                   // (i, k*PAD+j), zero-padded
__device__ float g_A  [BB*NN_*W3LD];                // (b, x, k*PAD+j)   ~147 MB
__device__ float g_C  [BB*NN_*PP*NN_];              // (b, x, k, y)      ~134 MB

// ---------------------------------------------------------------------------
// init: build padded W3 (k-inner relayout is identity here: W3 is (i,k,j)
// row-major already, we only pad i and j to 136)
// ---------------------------------------------------------------------------
__global__ void build_w3p_kernel(const float* __restrict__ W3)
{
    int idx = blockIdx.x * blockDim.x + threadIdx.x;
    const int total = PAD * W3LD;
    if (idx >= total) return;
    int i = idx / W3LD;
    int n = idx - i * W3LD;
    int k = n / PAD;
    int j = n - k * PAD;
    float v = 0.f;
    if (i < P1 && j < P1)
        v = W3[((size_t)i * PP + k) * P1 + j];   // W3 shape (129,128,129)
    g_W3p[idx] = v;
}

__global__ void pad_init_kernel()
{
    int r = blockIdx.x * blockDim.x + threadIdx.x;
    if (r >= BB * NN_) return;
    #pragma unroll
    for (int c = P1; c < PAD; c++) {
        g_x1p[(size_t)r * PAD + c] = 0.f;
        g_y1p[(size_t)r * PAD + c] = 0.f;
    }
    g_x1p[(size_t)r * PAD + PP] = 1.f;   // bias_x column
    g_y1p[(size_t)r * PAD + PP] = 1.f;   // bias_y column
}

// ---------------------------------------------------------------------------
// Stage 0: the three MLPs (rows=2048, cols=128, K=1024), fused via gridDim.z.
// out = leaky_relu(in @ W^T + b, 0.1). 64x64 tile, 256 thr, 4x4 microtile.
// ---------------------------------------------------------------------------
__global__ __launch_bounds__(256) void mlp_kernel(
    const float* __restrict__ x,  const float* __restrict__ xs,
    const float* __restrict__ Wx, const float* __restrict__ bx,
    const float* __restrict__ Wy, const float* __restrict__ by,
    const float* __restrict__ Wz, const float* __restrict__ bz)
{
    const float *in, *W, *bias; float* outp; int ldo;
    if (blockIdx.z == 0)      { in = xs; W = Wx; bias = bx; outp = g_x1p; ldo = PAD; }
    else if (blockIdx.z == 1) { in = xs; W = Wy; bias = by; outp = g_y1p; ldo = PAD; }
    else                      { in = x;  W = Wz; bias = bz; outp = g_zp;  ldo = PP;  }

    __shared__ __align__(16) float As[8][64];
    __shared__ __align__(16) float Bs[8][64];
    const int t  = threadIdx.x;
    const int m0 = blockIdx.x * 64, n0 = blockIdx.y * 64;
    const int tr = t >> 4, tc = t & 15;
    const int lrow = t >> 2, lk = (t & 3) * 2;

    float acc[4][4] = {};
    for (int k0 = 0; k0 < DD; k0 += 8) {
        float2 a = *reinterpret_cast<const float2*>(&in[(size_t)(m0 + lrow) * DD + k0 + lk]);
        float2 w = *reinterpret_cast<const float2*>(&W [(size_t)(n0 + lrow) * DD + k0 + lk]);
        __syncthreads();
        As[lk][lrow] = a.x; As[lk + 1][lrow] = a.y;
        Bs[lk][lrow] = w.x; Bs[lk + 1][lrow] = w.y;
        __syncthreads();
        #pragma unroll
        for (int kk = 0; kk < 8; kk++) {
            float4 av = *reinterpret_cast<float4*>(&As[kk][tr * 4]);
            float4 bv = *reinterpret_cast<float4*>(&Bs[kk][tc * 4]);
            float af[4] = {av.x, av.y, av.z, av.w};
            float bf[4] = {bv.x, bv.y, bv.z, bv.w};
            #pragma unroll
            for (int i = 0; i < 4; i++)
                #pragma unroll
                for (int j = 0; j < 4; j++)
                    acc[i][j] += af[i] * bf[j];
        }
    }
    #pragma unroll
    for (int i = 0; i < 4; i++) {
        int r = m0 + tr * 4 + i;
        #pragma unroll
        for (int j = 0; j < 4; j++) {
            int c = n0 + tc * 4 + j;
            float v = acc[i][j] + bias[c];
            v = (v > 0.f) ? v : 0.1f * v;
            outp[(size_t)r * ldo + c] = v;
        }
    }
}

// ---------------------------------------------------------------------------
// Stage 1: A_b = x1p_b (128 x 136) @ W3p (136 x 17408).   NN GEMM.
// One block per (128-col tile, b). 128x128 tile, 256 thr, 8x8 microtile.
// ---------------------------------------------------------------------------
__global__ __launch_bounds__(256, 2) void s1_kernel()
{
    const int b  = blockIdx.y;
    const int n0 = blockIdx.x * 128;
    const float* __restrict__ Ab = g_x1p + (size_t)b * NN_ * PAD;

    __shared__ __align__(16) float As[8][128];
    __shared__ __align__(16) float Bs[8][128];
    const int t = threadIdx.x;
    const int tr = t >> 4, tc = t & 15;
    const int arow = t >> 1, ak = (t & 1) * 4;       // K-contig operand -> transpose on store
    const int bkk  = t >> 5, bc = (t & 31) * 4;      // N-contig operand -> direct vector store

    float acc[8][8] = {};
    for (int k0 = 0; k0 < PAD; k0 += 8) {
        float4 av = *reinterpret_cast<const float4*>(&Ab[(size_t)arow * PAD + k0 + ak]);
        float4 bv = *reinterpret_cast<const float4*>(&g_W3p[(size_t)(k0 + bkk) * W3LD + n0 + bc]);
        __syncthreads();
        As[ak + 0][arow] = av.x; As[ak + 1][arow] = av.y;
        As[ak + 2][arow] = av.z; As[ak + 3][arow] = av.w;
        *reinterpret_cast<float4*>(&Bs[bkk][bc]) = bv;
        __syncthreads();
        #pragma unroll
        for (int kk = 0; kk < 8; kk++) {
            float4 a0 = *reinterpret_cast<float4*>(&As[kk][tr * 8]);
            float4 a1 = *reinterpret_cast<float4*>(&As[kk][tr * 8 + 4]);
            float4 b0 = *reinterpret_cast<float4*>(&Bs[kk][tc * 8]);
            float4 b1 = *reinterpret_cast<float4*>(&Bs[kk][tc * 8 + 4]);
            float af[8] = {a0.x, a0.y, a0.z, a0.w, a1.x, a1.y, a1.z, a1.w};
            float bf[8] = {b0.x, b0.y, b0.z, b0.w, b1.x, b1.y, b1.z, b1.w};
            #pragma unroll
            for (int i = 0; i < 8; i++)
                #pragma unroll
                for (int j = 0; j < 8; j++)
                    acc[i][j] += af[i] * bf[j];
        }
    }
    float* __restrict__ Ob = g_A + (size_t)b * NN_ * W3LD;
    #pragma unroll
    for (int i = 0; i < 8; i++) {
        int r = tr * 8 + i;
        float4 v0 = {acc[i][0], acc[i][1], acc[i][2], acc[i][3]};
        float4 v1 = {acc[i][4], acc[i][5], acc[i][6], acc[i][7]};
        float* p = &Ob[(size_t)r * W3LD + n0 + tc * 8];
        *reinterpret_cast<float4*>(p)     = v0;
        *reinterpret_cast<float4*>(p + 4) = v1;
    }
}

// ---------------------------------------------------------------------------
// Stage 2: C[b, (x,k), y] = A[b, (x,k), j] . y1p[b, y, j].  NT GEMM, K=136.
// Rows r=(x*128+k) of g_A (ld=PAD since 128*PAD=W3LD). 128x128 tile.
// ---------------------------------------------------------------------------
__global__ __launch_bounds__(256, 2) void s2_kernel()
{
    const int b  = blockIdx.y;
    const int r0 = blockIdx.x * 128;
    const float* __restrict__ Ab = g_A   + (size_t)b * NN_ * W3LD;
    const float* __restrict__ Yb = g_y1p + (size_t)b * NN_ * PAD;

    __shared__ __align__(16) float As[8][128];
    __shared__ __align__(16) float Bs[8][128];
    const int t = threadIdx.x;
    const int tr = t >> 4, tc = t & 15;
    const int lrow = t >> 1, lk = (t & 1) * 4;

    float acc[8][8] = {};
    for (int k0 = 0; k0 < PAD; k0 += 8) {
        float4 av = *reinterpret_cast<const float4*>(&Ab[(size_t)(r0 + lrow) * PAD + k0 + lk]);
        float4 yv = *reinterpret_cast<const float4*>(&Yb[(size_t)lrow * PAD + k0 + lk]);
        __syncthreads();
        As[lk + 0][lrow] = av.x; As[lk + 1][lrow] = av.y;
        As[lk + 2][lrow] = av.z; As[lk + 3][lrow] = av.w;
        Bs[lk + 0][lrow] = yv.x; Bs[lk + 1][lrow] = yv.y;
        Bs[lk + 2][lrow] = yv.z; Bs[lk + 3][lrow] = yv.w;
        __syncthreads();
        #pragma unroll
        for (int kk = 0; kk < 8; kk++) {
            float4 a0 = *reinterpret_cast<float4*>(&As[kk][tr * 8]);
            float4 a1 = *reinterpret_cast<float4*>(&As[kk][tr * 8 + 4]);
            float4 b0 = *reinterpret_cast<float4*>(&Bs[kk][tc * 8]);
            float4 b1 = *reinterpret_cast<float4*>(&Bs[kk][tc * 8 + 4]);
            float af[8] = {a0.x, a0.y, a0.z, a0.w, a1.x, a1.y, a1.z, a1.w};
            float bf[8] = {b0.x, b0.y, b0.z, b0.w, b1.x, b1.y, b1.z, b1.w};
            #pragma unroll
            for (int i = 0; i < 8; i++)
                #pragma unroll
                for (int j = 0; j < 8; j++)
                    acc[i][j] += af[i] * bf[j];
        }
    }
    float* __restrict__ Ob = g_C + ((size_t)b * NN_ * PP + r0) * NN_;
    #pragma unroll
    for (int i = 0; i < 8; i++) {
        int r = tr * 8 + i;
        float4 v0 = {acc[i][0], acc[i][1], acc[i][2], acc[i][3]};
        float4 v1 = {acc[i][4], acc[i][5], acc[i][6], acc[i][7]};
        float* p = &Ob[(size_t)r * NN_ + tc * 8];
        *reinterpret_cast<float4*>(p)     = v0;
        *reinterpret_cast<float4*>(p + 4) = v1;
    }
}

// ---------------------------------------------------------------------------
// Stage 3: out[b,x,y,z] = sum_k C[b,x,k,y] * zp[b,z,k].  One block per (b,x).
// C tile rows are k (y contiguous -> direct load); zp is K-contig -> transpose.
// Output tile (y,z) is fully contiguous -> coalesced float4 stores, no extra
// transpose pass needed.
// ---------------------------------------------------------------------------
__global__ __launch_bounds__(256, 2) void s3_kernel(float* __restrict__ out)
{
    const int b  = blockIdx.y;
    const int xx = blockIdx.x;
    const float* __restrict__ Cm = g_C  + ((size_t)b * NN_ + xx) * (PP * NN_); // [k*128 + y]
    const float* __restrict__ Zb = g_zp + (size_t)b * NN_ * PP;                // [z*128 + k]

    __shared__ __align__(16) float Cs[8][128];
    __shared__ __align__(16) float Zs[8][128];
    const int t = threadIdx.x;
    const int tr = t >> 4, tc = t & 15;
    const int ckk  = t >> 5, cy = (t & 31) * 4;
    const int zrow = t >> 1, zk = (t & 1) * 4;

    float acc[8][8] = {};
    for (int k0 = 0; k0 < PP; k0 += 8) {
        float4 cv = *reinterpret_cast<const float4*>(&Cm[(size_t)(k0 + ckk) * NN_ + cy]);
        float4 zv = *reinterpret_cast<const float4*>(&Zb[(size_t)zrow * PP + k0 + zk]);
        __syncthreads();
        *reinterpret_cast<float4*>(&Cs[ckk][cy]) = cv;
        Zs[zk + 0][zrow] = zv.x; Zs[zk + 1][zrow] = zv.y;
        Zs[zk + 2][zrow] = zv.z; Zs[zk + 3][zrow] = zv.w;
        __syncthreads();
        #pragma unroll
        for (int kk = 0; kk < 8; kk++) {
            float4 a0 = *reinterpret_cast<float4*>(&Cs[kk][tr * 8]);      // y fragment
            float4 a1 = *reinterpret_cast<float4*>(&Cs[kk][tr * 8 + 4]);
            float4 b0 = *reinterpret_cast<float4*>(&Zs[kk][tc * 8]);      // z fragment
            float4 b1 = *reinterpret_cast<float4*>(&Zs[kk][tc * 8 + 4]);
            float af[8] = {a0.x, a0.y, a0.z, a0.w, a1.x, a1.y, a1.z, a1.w};
            float bf[8] = {b0.x, b0.y, b0.z, b0.w, b1.x, b1.y, b1.z, b1.w};
            #pragma unroll
            for (int i = 0; i < 8; i++)
                #pragma unroll
                for (int j = 0; j < 8; j++)
                    acc[i][j] += af[i] * bf[j];
        }
    }
    float* __restrict__ Ob = out + ((size_t)b * NN_ + xx) * (NN_ * PP);
    #pragma unroll
    for (int i = 0; i < 8; i++) {
        int y = tr * 8 + i;
        float4 v0 = {acc[i][0], acc[i][1], acc[i][2], acc[i][3]};
        float4 v1 = {acc[i][4], acc[i][5], acc[i][6], acc[i][7]};
        float* p = &Ob[(size_t)y * PP + tc * 8];
        *reinterpret_cast<float4*>(p)     = v0;
        *reinterpret_cast<float4*>(p + 4) = v1;
    }
}

// ---------------------------------------------------------------------------
extern "C" void kernel_launch(void* const* d_in, const int* in_sizes, int n_in,
                              void* d_out, int out_size)
{
    const float* x  = (const float*)d_in[0];
    const float* xs = (const float*)d_in[1];
    const float* Wx = (const float*)d_in[2];
    const float* bx = (const float*)d_in[3];
    const float* Wy = (const float*)d_in[4];
    const float* by = (const float*)d_in[5];
    const float* Wz = (const float*)d_in[6];
    const float* bz = (const float*)d_in[7];
    const float* W3 = (const float*)d_in[8];
    float* out = (float*)d_out;

    const int w3p_total = PAD * W3LD;
    build_w3p_kernel<<<(w3p_total + 255) / 256, 256>>>(W3);
    pad_init_kernel<<<(BB * NN_ + 255) / 256, 256>>>();
    mlp_kernel<<<dim3(BB * NN_ / 64, PP / 64, 3), 256>>>(x, xs, Wx, bx, Wy, by, Wz, bz);
    s1_kernel<<<dim3(W3LD / 128, BB), 256>>>();
    s2_kernel<<<dim3(NN_ * PP / 128, BB), 256>>>();
    s3_kernel<<<dim3(NN_, BB), 256>>>(out);
}